// round 5
// baseline (speedup 1.0000x reference)
#include <cuda_runtime.h>
#include <cuda_bf16.h>

// SparseCrop: coords (N,4) int32, feats (N,C=64) float32.
// mask[i] = all(10 <= coords[i, 0:3] < 90)   (~51.2% pass rate)
// out_feats = feats * mask[:, None]
// Output layout (float32): [out_feats (N*C), mask (N)].
//
// R4 state: 70.7us kernel, DRAM 62%. This round: UNROLL 4->8 (deeper
// front-batch of independent coords->mask->load chains) + __ldcs streaming
// reads (feats are read-once; keep L2 free for the 256MB write stream).

#define UNROLL 8

__global__ void sparse_crop_kernel(const int4* __restrict__ coords,
                                   const float4* __restrict__ feats,
                                   float4* __restrict__ out_feats,
                                   float* __restrict__ mask_out,
                                   int n_vec4,          // N * (C/4)
                                   int row_shift,       // log2(C/4)
                                   int row_mask,        // (C/4) - 1
                                   int write_mask)
{
    int base = blockIdx.x * (blockDim.x * UNROLL) + threadIdx.x;

    bool   m[UNROLL];
    float4 f[UNROLL];

    // Phase 1: masks + batched predicated streaming loads
    #pragma unroll
    for (int k = 0; k < UNROLL; k++) {
        int idx = base + k * blockDim.x;
        m[k] = false;
        f[k] = make_float4(0.f, 0.f, 0.f, 0.f);
        if (idx < n_vec4) {
            int4 c = coords[idx >> row_shift];
            // 10 <= v < 90  <=>  (unsigned)(v - 10) < 80
            m[k] = ((unsigned)(c.x - 10) < 80u) &&
                   ((unsigned)(c.y - 10) < 80u) &&
                   ((unsigned)(c.z - 10) < 80u);
            if (m[k]) {
                f[k] = __ldcs(&feats[idx]);   // read-once: evict-first
            }
        }
    }

    // Phase 2: streaming stores
    #pragma unroll
    for (int k = 0; k < UNROLL; k++) {
        int idx = base + k * blockDim.x;
        if (idx < n_vec4) {
            __stcs(&out_feats[idx], f[k]);
            if (write_mask && (idx & row_mask) == 0) {
                mask_out[idx >> row_shift] = m[k] ? 1.0f : 0.0f;
            }
        }
    }
}

// Fallback for non-power-of-two C/4 (shape-variant safety).
__global__ void sparse_crop_kernel_div(const int4* __restrict__ coords,
                                       const float4* __restrict__ feats,
                                       float4* __restrict__ out_feats,
                                       float* __restrict__ mask_out,
                                       int n_vec4,
                                       int vecs_per_row,
                                       int write_mask)
{
    int idx = blockIdx.x * blockDim.x + threadIdx.x;
    if (idx >= n_vec4) return;

    int row = idx / vecs_per_row;
    int4 c = coords[row];
    bool m = ((unsigned)(c.x - 10) < 80u) &&
             ((unsigned)(c.y - 10) < 80u) &&
             ((unsigned)(c.z - 10) < 80u);

    float4 f = make_float4(0.f, 0.f, 0.f, 0.f);
    if (m) {
        f = __ldcs(&feats[idx]);
    }
    __stcs(&out_feats[idx], f);

    if (write_mask && (idx - row * vecs_per_row) == 0) {
        mask_out[row] = m ? 1.0f : 0.0f;
    }
}

extern "C" void kernel_launch(void* const* d_in, const int* in_sizes, int n_in,
                              void* d_out, int out_size)
{
    const int* coords = (const int*)d_in[0];     // (N, 4) int32
    const float* feats = (const float*)d_in[1];  // (N, C) float32
    float* out = (float*)d_out;

    int N = in_sizes[0] / 4;
    int C = in_sizes[1] / N;          // 64
    int vecs_per_row = C / 4;         // 16
    int n_vec4 = N * vecs_per_row;

    int write_mask = (out_size >= N * C + N) ? 1 : 0;
    float* mask_out = out + (size_t)N * C;

    int threads = 256;

    bool pow2 = (vecs_per_row & (vecs_per_row - 1)) == 0;
    if (pow2) {
        int shift = 0;
        while ((1 << shift) < vecs_per_row) shift++;
        int tile = threads * UNROLL;
        int blocks = (n_vec4 + tile - 1) / tile;
        sparse_crop_kernel<<<blocks, threads>>>(
            (const int4*)coords, (const float4*)feats,
            (float4*)out, mask_out,
            n_vec4, shift, vecs_per_row - 1, write_mask);
    } else {
        int blocks = (n_vec4 + threads - 1) / threads;
        sparse_crop_kernel_div<<<blocks, threads>>>(
            (const int4*)coords, (const float4*)feats,
            (float4*)out, mask_out,
            n_vec4, vecs_per_row, write_mask);
    }
}

// round 9
// speedup vs baseline: 1.3173x; 1.3173x over previous
#include <cuda_runtime.h>
#include <cuda_bf16.h>

// SparseCrop: coords (N,4) int32, feats (N,C=64) float32.
// mask[i] = all(10 <= coords[i, 0:3] < 90)   (~51.2% pass rate)
// out_feats = feats * mask[:, None]
// Output layout (float32): [out_feats (N*C), mask (N)].
//
// R5 post-mortem: UNROLL=8 blew registers (54) -> occ 45% -> regression.
// This round: exact R4 structure (UNROLL=4, regs 32, occ 84%, 70.7us)
// with ONE change: __ldcs on the read-once feats load (evict-first, keeps
// L2 free for the 256MB write stream).

#define UNROLL 4

__global__ void sparse_crop_kernel(const int4* __restrict__ coords,
                                   const float4* __restrict__ feats,
                                   float4* __restrict__ out_feats,
                                   float* __restrict__ mask_out,
                                   int n_vec4,          // N * (C/4)
                                   int row_shift,       // log2(C/4)
                                   int row_mask,        // (C/4) - 1
                                   int write_mask)
{
    int base = blockIdx.x * (blockDim.x * UNROLL) + threadIdx.x;

    int   idx[UNROLL];
    bool  ok [UNROLL];
    bool  m  [UNROLL];
    float4 f [UNROLL];

    // Phase 1: masks + batched predicated streaming loads (front-batched MLP)
    #pragma unroll
    for (int k = 0; k < UNROLL; k++) {
        idx[k] = base + k * blockDim.x;
        ok[k]  = idx[k] < n_vec4;
        m[k]   = false;
        f[k]   = make_float4(0.f, 0.f, 0.f, 0.f);
        if (ok[k]) {
            int row = idx[k] >> row_shift;
            int4 c  = coords[row];
            // 10 <= v < 90  <=>  (unsigned)(v - 10) < 80
            m[k] = ((unsigned)(c.x - 10) < 80u) &&
                   ((unsigned)(c.y - 10) < 80u) &&
                   ((unsigned)(c.z - 10) < 80u);
            if (m[k]) {
                f[k] = __ldcs(&feats[idx[k]]);   // read-once: evict-first
            }
        }
    }

    // Phase 2: streaming stores
    #pragma unroll
    for (int k = 0; k < UNROLL; k++) {
        if (ok[k]) {
            __stcs(&out_feats[idx[k]], f[k]);
            if (write_mask && (idx[k] & row_mask) == 0) {
                mask_out[idx[k] >> row_shift] = m[k] ? 1.0f : 0.0f;
            }
        }
    }
}

// Fallback for non-power-of-two C/4 (shape-variant safety).
__global__ void sparse_crop_kernel_div(const int4* __restrict__ coords,
                                       const float4* __restrict__ feats,
                                       float4* __restrict__ out_feats,
                                       float* __restrict__ mask_out,
                                       int n_vec4,
                                       int vecs_per_row,
                                       int write_mask)
{
    int idx = blockIdx.x * blockDim.x + threadIdx.x;
    if (idx >= n_vec4) return;

    int row = idx / vecs_per_row;
    int4 c = coords[row];
    bool m = ((unsigned)(c.x - 10) < 80u) &&
             ((unsigned)(c.y - 10) < 80u) &&
             ((unsigned)(c.z - 10) < 80u);

    float4 f = make_float4(0.f, 0.f, 0.f, 0.f);
    if (m) {
        f = __ldcs(&feats[idx]);
    }
    __stcs(&out_feats[idx], f);

    if (write_mask && (idx - row * vecs_per_row) == 0) {
        mask_out[row] = m ? 1.0f : 0.0f;
    }
}

extern "C" void kernel_launch(void* const* d_in, const int* in_sizes, int n_in,
                              void* d_out, int out_size)
{
    const int* coords = (const int*)d_in[0];     // (N, 4) int32
    const float* feats = (const float*)d_in[1];  // (N, C) float32
    float* out = (float*)d_out;

    int N = in_sizes[0] / 4;
    int C = in_sizes[1] / N;          // 64
    int vecs_per_row = C / 4;         // 16
    int n_vec4 = N * vecs_per_row;

    int write_mask = (out_size >= N * C + N) ? 1 : 0;
    float* mask_out = out + (size_t)N * C;

    int threads = 256;

    bool pow2 = (vecs_per_row & (vecs_per_row - 1)) == 0;
    if (pow2) {
        int shift = 0;
        while ((1 << shift) < vecs_per_row) shift++;
        int tile = threads * UNROLL;
        int blocks = (n_vec4 + tile - 1) / tile;
        sparse_crop_kernel<<<blocks, threads>>>(
            (const int4*)coords, (const float4*)feats,
            (float4*)out, mask_out,
            n_vec4, shift, vecs_per_row - 1, write_mask);
    } else {
        int blocks = (n_vec4 + threads - 1) / threads;
        sparse_crop_kernel_div<<<blocks, threads>>>(
            (const int4*)coords, (const float4*)feats,
            (float4*)out, mask_out,
            n_vec4, vecs_per_row, write_mask);
    }
}

// round 11
// speedup vs baseline: 1.3702x; 1.0401x over previous
#include <cuda_runtime.h>
#include <cuda_bf16.h>

// SparseCrop: coords (N,4) int32, feats (N,C=64) float32.
// mask[i] = all(10 <= coords[i, 0:3] < 90)   (~51.2% pass rate)
// out_feats = feats * mask[:, None]
// Output layout (float32): [out_feats (N*C), mask (N)].
//
// R9 baseline: UNROLL=4 float4 + __ldcs/__stcs, 69.9us kernel, DRAM 62.8%,
// regs 32, occ 83.5%. This round (single variable): 256-bit global accesses
// (ld/st.global.v8.f32, sm_100+) — 2x32B per thread instead of 4x16B. Same
// outstanding bytes & registers, half the LSU/L1tex transactions.

#define UNROLL 2   // v8 chunks per thread (2 x 32B = 64B, same as R9's 4 x 16B)

__device__ __forceinline__ void ldg_cs_v8(const float* __restrict__ p, float r[8]) {
    asm volatile("ld.global.cs.v8.f32 {%0,%1,%2,%3,%4,%5,%6,%7}, [%8];"
                 : "=f"(r[0]), "=f"(r[1]), "=f"(r[2]), "=f"(r[3]),
                   "=f"(r[4]), "=f"(r[5]), "=f"(r[6]), "=f"(r[7])
                 : "l"(p));
}

__device__ __forceinline__ void stg_cs_v8(float* p, const float r[8]) {
    asm volatile("st.global.cs.v8.f32 [%0], {%1,%2,%3,%4,%5,%6,%7,%8};"
                 :: "l"(p), "f"(r[0]), "f"(r[1]), "f"(r[2]), "f"(r[3]),
                    "f"(r[4]), "f"(r[5]), "f"(r[6]), "f"(r[7])
                 : "memory");
}

__global__ void sparse_crop_v8_kernel(const int4* __restrict__ coords,
                                      const float* __restrict__ feats,
                                      float* __restrict__ out_feats,
                                      float* __restrict__ mask_out,
                                      int n_vec8,        // N * (C/8)
                                      int row_shift,     // log2(C/8)
                                      int row_mask,      // (C/8) - 1
                                      int write_mask)
{
    int base = blockIdx.x * (blockDim.x * UNROLL) + threadIdx.x;

    bool  m[UNROLL];
    float f[UNROLL][8];

    // Phase 1: masks + batched predicated 256-bit streaming loads
    #pragma unroll
    for (int k = 0; k < UNROLL; k++) {
        int idx = base + k * blockDim.x;
        m[k] = false;
        #pragma unroll
        for (int j = 0; j < 8; j++) f[k][j] = 0.f;
        if (idx < n_vec8) {
            int4 c = coords[idx >> row_shift];
            // 10 <= v < 90  <=>  (unsigned)(v - 10) < 80
            m[k] = ((unsigned)(c.x - 10) < 80u) &&
                   ((unsigned)(c.y - 10) < 80u) &&
                   ((unsigned)(c.z - 10) < 80u);
            if (m[k]) {
                ldg_cs_v8(feats + (size_t)idx * 8, f[k]);
            }
        }
    }

    // Phase 2: 256-bit streaming stores
    #pragma unroll
    for (int k = 0; k < UNROLL; k++) {
        int idx = base + k * blockDim.x;
        if (idx < n_vec8) {
            stg_cs_v8(out_feats + (size_t)idx * 8, f[k]);
            if (write_mask && (idx & row_mask) == 0) {
                mask_out[idx >> row_shift] = m[k] ? 1.0f : 0.0f;
            }
        }
    }
}

// Fallback (float4 path) for shapes where C % 8 != 0 or C/8 not pow2.
__global__ void sparse_crop_kernel_div(const int4* __restrict__ coords,
                                       const float4* __restrict__ feats,
                                       float4* __restrict__ out_feats,
                                       float* __restrict__ mask_out,
                                       int n_vec4,
                                       int vecs_per_row,
                                       int write_mask)
{
    int idx = blockIdx.x * blockDim.x + threadIdx.x;
    if (idx >= n_vec4) return;

    int row = idx / vecs_per_row;
    int4 c = coords[row];
    bool m = ((unsigned)(c.x - 10) < 80u) &&
             ((unsigned)(c.y - 10) < 80u) &&
             ((unsigned)(c.z - 10) < 80u);

    float4 f = make_float4(0.f, 0.f, 0.f, 0.f);
    if (m) {
        f = __ldcs(&feats[idx]);
    }
    __stcs(&out_feats[idx], f);

    if (write_mask && (idx - row * vecs_per_row) == 0) {
        mask_out[row] = m ? 1.0f : 0.0f;
    }
}

extern "C" void kernel_launch(void* const* d_in, const int* in_sizes, int n_in,
                              void* d_out, int out_size)
{
    const int* coords = (const int*)d_in[0];     // (N, 4) int32
    const float* feats = (const float*)d_in[1];  // (N, C) float32
    float* out = (float*)d_out;

    int N = in_sizes[0] / 4;
    int C = in_sizes[1] / N;          // 64
    int write_mask = (out_size >= N * C + N) ? 1 : 0;
    float* mask_out = out + (size_t)N * C;

    int threads = 256;

    int vecs8 = C / 8;
    bool v8ok = (C % 8 == 0) && ((vecs8 & (vecs8 - 1)) == 0);

    if (v8ok) {
        int shift = 0;
        while ((1 << shift) < vecs8) shift++;
        int n_vec8 = N * vecs8;
        int tile = threads * UNROLL;
        int blocks = (n_vec8 + tile - 1) / tile;
        sparse_crop_v8_kernel<<<blocks, threads>>>(
            (const int4*)coords, feats, out, mask_out,
            n_vec8, shift, vecs8 - 1, write_mask);
    } else {
        int vecs_per_row = C / 4;
        int n_vec4 = N * vecs_per_row;
        int blocks = (n_vec4 + threads - 1) / threads;
        sparse_crop_kernel_div<<<blocks, threads>>>(
            (const int4*)coords, (const float4*)feats,
            (float4*)out, mask_out,
            n_vec4, vecs_per_row, write_mask);
    }
}